// round 5
// baseline (speedup 1.0000x reference)
#include <cuda_runtime.h>
#include <math.h>

#define S_LEN  2048
#define B_SZ   4
#define DMODEL 512
#define DK     64
#define BM     128      // query rows per attention block (== threads)
#define KC     256      // keys per split-KV chunk
#define SUBK   64       // keys per SMEM subtile
#define NT     (S_LEN / BM)   // 16 query tiles per batch
#define MAXCH  (S_LEN / KC)   // 8 chunks max

// ------------------------- scratch (no mallocs allowed) -------------------------
__device__ float g_q   [B_SZ * S_LEN * DK];
__device__ float g_k   [B_SZ * S_LEN * DK];
__device__ float g_v   [B_SZ * S_LEN * DK];
__device__ float g_ho  [B_SZ * S_LEN * DK];
__device__ float g_weff[DK * DMODEL];
__device__ float g_po  [(size_t)B_SZ * NT * MAXCH * BM * DK];
__device__ float g_pml [(size_t)B_SZ * NT * MAXCH * BM * 2];

// ------------------------- 1) fused q/k/v projections -------------------------
// GEMM: out[8192,64] = X[8192,512] @ W[512,64] + b.  blockIdx.z selects q/k/v.
// Tile: 64 rows x 64 cols, 256 threads (16x16), 4x4 microtile, K-tile 32.
__global__ __launch_bounds__(256) void proj_kernel(
    const float* __restrict__ Q, const float* __restrict__ K, const float* __restrict__ V,
    const float* __restrict__ WQ, const float* __restrict__ bQ,
    const float* __restrict__ WK, const float* __restrict__ bK,
    const float* __restrict__ WV, const float* __restrict__ bV)
{
    const float* X; const float* W; const float* bias; float* out;
    if (blockIdx.z == 0)      { X = Q; W = WQ; bias = bQ; out = g_q; }
    else if (blockIdx.z == 1) { X = K; W = WK; bias = bK; out = g_k; }
    else                      { X = V; W = WV; bias = bV; out = g_v; }

    __shared__ float Xs[64][33];   // padded: avoid bank conflict on row reads
    __shared__ float Ws[32][64];

    const int tid = threadIdx.x;
    const int tx = tid & 15, ty = tid >> 4;
    const int m0 = blockIdx.x * 64;

    float acc[4][4] = {};

    for (int k0 = 0; k0 < DMODEL; k0 += 32) {
        __syncthreads();
        // Xs: 64 rows x 32 cols = 512 float4
        #pragma unroll
        for (int it = 0; it < 2; it++) {
            int idx = tid + it * 256;          // 0..511
            int row = idx >> 3;                // 8 float4 per row
            int c4  = idx & 7;
            float4 v4 = *(const float4*)(X + (size_t)(m0 + row) * DMODEL + k0 + c4 * 4);
            Xs[row][c4 * 4 + 0] = v4.x; Xs[row][c4 * 4 + 1] = v4.y;
            Xs[row][c4 * 4 + 2] = v4.z; Xs[row][c4 * 4 + 3] = v4.w;
        }
        // Ws: 32 rows x 64 cols = 512 float4
        #pragma unroll
        for (int it = 0; it < 2; it++) {
            int idx = tid + it * 256;
            int row = idx >> 4;                // 16 float4 per row
            int c4  = idx & 15;
            float4 v4 = *(const float4*)(W + (size_t)(k0 + row) * DK + c4 * 4);
            *(float4*)&Ws[row][c4 * 4] = v4;
        }
        __syncthreads();

        #pragma unroll
        for (int kk = 0; kk < 32; kk++) {
            float a0 = Xs[ty * 4 + 0][kk];
            float a1 = Xs[ty * 4 + 1][kk];
            float a2 = Xs[ty * 4 + 2][kk];
            float a3 = Xs[ty * 4 + 3][kk];
            float4 b4 = *(const float4*)&Ws[kk][tx * 4];
            acc[0][0] = fmaf(a0, b4.x, acc[0][0]); acc[0][1] = fmaf(a0, b4.y, acc[0][1]);
            acc[0][2] = fmaf(a0, b4.z, acc[0][2]); acc[0][3] = fmaf(a0, b4.w, acc[0][3]);
            acc[1][0] = fmaf(a1, b4.x, acc[1][0]); acc[1][1] = fmaf(a1, b4.y, acc[1][1]);
            acc[1][2] = fmaf(a1, b4.z, acc[1][2]); acc[1][3] = fmaf(a1, b4.w, acc[1][3]);
            acc[2][0] = fmaf(a2, b4.x, acc[2][0]); acc[2][1] = fmaf(a2, b4.y, acc[2][1]);
            acc[2][2] = fmaf(a2, b4.z, acc[2][2]); acc[2][3] = fmaf(a2, b4.w, acc[2][3]);
            acc[3][0] = fmaf(a3, b4.x, acc[3][0]); acc[3][1] = fmaf(a3, b4.y, acc[3][1]);
            acc[3][2] = fmaf(a3, b4.z, acc[3][2]); acc[3][3] = fmaf(a3, b4.w, acc[3][3]);
        }
    }

    float4 bb = *(const float4*)&bias[tx * 4];
    #pragma unroll
    for (int i = 0; i < 4; i++) {
        float4 r = make_float4(acc[i][0] + bb.x, acc[i][1] + bb.y,
                               acc[i][2] + bb.z, acc[i][3] + bb.w);
        *(float4*)&out[(size_t)(m0 + ty * 4 + i) * DK + tx * 4] = r;
    }
}

// ------------------------- 2) W_eff = sum over 8 head-blocks of Wo_w ----------
// tile(head_out, 8) @ Wo == head_out @ (sum of 8 row-blocks of Wo)
__global__ void weff_kernel(const float* __restrict__ Wo) {
    int idx = blockIdx.x * 256 + threadIdx.x;  // 64*512 = 32768 elements
    int r = idx >> 9;
    int c = idx & 511;
    float s = 0.f;
    #pragma unroll
    for (int h = 0; h < 8; h++) s += Wo[(size_t)((h << 6) + r) * DMODEL + c];
    g_weff[idx] = s;
}

// ------------------------- 3) split-KV flash attention partials ---------------
// One thread owns one query row: q[64], o[64] in registers. K/V subtiles in SMEM.
__global__ __launch_bounds__(128, 3) void attn_partial_kernel() {
    const int b = blockIdx.z;
    const int t = blockIdx.y;
    const int chunk = blockIdx.x;
    const int kbeg = chunk * KC;
    const int kend = min(kbeg + KC, (t + 1) * BM);
    if (kbeg >= kend) return;  // uniform across block (no sync before this)

    const int tid = threadIdx.x;
    const int qrow = t * BM + tid;

    const float* qptr = g_q + ((size_t)b * S_LEN + qrow) * DK;
    float q[DK];
    #pragma unroll
    for (int i = 0; i < DK / 4; i++) {
        float4 v4 = ((const float4*)qptr)[i];
        q[i * 4 + 0] = v4.x; q[i * 4 + 1] = v4.y;
        q[i * 4 + 2] = v4.z; q[i * 4 + 3] = v4.w;
    }

    __shared__ float Ks[SUBK][DK];
    __shared__ float Vs[SUBK][DK];

    float m = -INFINITY, l = 0.f;
    float o[DK];
    #pragma unroll
    for (int d = 0; d < DK; d++) o[d] = 0.f;

    const int lrow = tid >> 1, half = tid & 1;

    for (int ks = kbeg; ks < kend; ks += SUBK) {
        __syncthreads();
        {   // cooperative load: 64 rows x 64 floats each for K and V
            const float4* kg = (const float4*)(g_k + ((size_t)b * S_LEN + ks + lrow) * DK + half * 32);
            const float4* vg = (const float4*)(g_v + ((size_t)b * S_LEN + ks + lrow) * DK + half * 32);
            float4* kd = (float4*)&Ks[lrow][half * 32];
            float4* vd = (float4*)&Vs[lrow][half * 32];
            #pragma unroll
            for (int i = 0; i < 8; i++) kd[i] = kg[i];
            #pragma unroll
            for (int i = 0; i < 8; i++) vd[i] = vg[i];
        }
        __syncthreads();

        #pragma unroll 1
        for (int j = 0; j < SUBK; j++) {
            if (ks + j > qrow) break;  // causal: all further keys masked for this row
            float s0 = 0.f, s1 = 0.f, s2 = 0.f, s3 = 0.f;
            #pragma unroll
            for (int d = 0; d < DK; d += 4) {
                float4 k4 = *(const float4*)&Ks[j][d];
                s0 = fmaf(q[d + 0], k4.x, s0);
                s1 = fmaf(q[d + 1], k4.y, s1);
                s2 = fmaf(q[d + 2], k4.z, s2);
                s3 = fmaf(q[d + 3], k4.w, s3);
            }
            float s = ((s0 + s1) + (s2 + s3)) * 0.125f;  // 1/sqrt(64)

            float mn = fmaxf(m, s);
            if (mn > m) {             // rare online-softmax rescale
                float cor = __expf(m - mn);   // m=-inf first time -> 0, o already 0
                l *= cor;
                #pragma unroll
                for (int d = 0; d < DK; d++) o[d] *= cor;
                m = mn;
            }
            float p = __expf(s - m);
            l += p;
            #pragma unroll
            for (int d = 0; d < DK; d += 4) {
                float4 v4 = *(const float4*)&Vs[j][d];
                o[d + 0] = fmaf(p, v4.x, o[d + 0]);
                o[d + 1] = fmaf(p, v4.y, o[d + 1]);
                o[d + 2] = fmaf(p, v4.z, o[d + 2]);
                o[d + 3] = fmaf(p, v4.w, o[d + 3]);
            }
        }
    }

    const size_t base = (((size_t)b * NT + t) * MAXCH + chunk) * BM + tid;
    float* po = g_po + base * DK;
    #pragma unroll
    for (int d = 0; d < DK; d += 4)
        *(float4*)(po + d) = make_float4(o[d], o[d + 1], o[d + 2], o[d + 3]);
    g_pml[base * 2 + 0] = m;
    g_pml[base * 2 + 1] = l;
}

// ------------------------- 4) merge split-KV partials -------------------------
__global__ __launch_bounds__(128) void attn_merge_kernel() {
    const int b = blockIdx.y, t = blockIdx.x, tid = threadIdx.x;
    const int nch = ((t + 1) * BM + KC - 1) / KC;  // active chunks for this tile
    const size_t base0 = (((size_t)b * NT + t) * MAXCH) * BM + tid;

    float mstar = -INFINITY;
    for (int c = 0; c < nch; c++)
        mstar = fmaxf(mstar, g_pml[(base0 + (size_t)c * BM) * 2]);

    float lsum = 0.f;
    float o[DK];
    #pragma unroll
    for (int d = 0; d < DK; d++) o[d] = 0.f;

    for (int c = 0; c < nch; c++) {
        size_t bb = base0 + (size_t)c * BM;
        float mc = g_pml[bb * 2 + 0];
        float lc = g_pml[bb * 2 + 1];
        float w = __expf(mc - mstar);
        lsum += lc * w;
        const float4* po = (const float4*)(g_po + bb * DK);
        #pragma unroll
        for (int i = 0; i < DK / 4; i++) {
            float4 v4 = po[i];
            o[i * 4 + 0] = fmaf(w, v4.x, o[i * 4 + 0]);
            o[i * 4 + 1] = fmaf(w, v4.y, o[i * 4 + 1]);
            o[i * 4 + 2] = fmaf(w, v4.z, o[i * 4 + 2]);
            o[i * 4 + 3] = fmaf(w, v4.w, o[i * 4 + 3]);
        }
    }
    float inv = 1.f / lsum;
    float* out = g_ho + ((size_t)b * S_LEN + t * BM + tid) * DK;
    #pragma unroll
    for (int i = 0; i < DK / 4; i++)
        *(float4*)(out + i * 4) = make_float4(o[i * 4 + 0] * inv, o[i * 4 + 1] * inv,
                                              o[i * 4 + 2] * inv, o[i * 4 + 3] * inv);
}

// ------------------------- 5) output GEMM: ho @ W_eff + Wo_b ------------------
// out[8192,512] = ho[8192,64] @ g_weff[64,512] + b. Tile 64x64, K=64 one shot.
__global__ __launch_bounds__(256) void outproj_kernel(
    const float* __restrict__ Wo_b, float* __restrict__ out)
{
    __shared__ float As[64][65];
    __shared__ float Bs[64][64];

    const int tid = threadIdx.x;
    const int tx = tid & 15, ty = tid >> 4;
    const int m0 = blockIdx.x * 64;
    const int n0 = blockIdx.y * 64;

    // As: 64x64 = 1024 float4
    #pragma unroll
    for (int it = 0; it < 4; it++) {
        int idx = tid + it * 256;
        int row = idx >> 4;
        int c4  = idx & 15;
        float4 v4 = *(const float4*)(g_ho + (size_t)(m0 + row) * DK + c4 * 4);
        As[row][c4 * 4 + 0] = v4.x; As[row][c4 * 4 + 1] = v4.y;
        As[row][c4 * 4 + 2] = v4.z; As[row][c4 * 4 + 3] = v4.w;
    }
    // Bs: 64 rows (k) x 64 cols of g_weff
    #pragma unroll
    for (int it = 0; it < 4; it++) {
        int idx = tid + it * 256;
        int row = idx >> 4;
        int c4  = idx & 15;
        float4 v4 = *(const float4*)(g_weff + (size_t)row * DMODEL + n0 + c4 * 4);
        *(float4*)&Bs[row][c4 * 4] = v4;
    }
    __syncthreads();

    float acc[4][4] = {};
    #pragma unroll
    for (int kk = 0; kk < 64; kk++) {
        float a0 = As[ty * 4 + 0][kk];
        float a1 = As[ty * 4 + 1][kk];
        float a2 = As[ty * 4 + 2][kk];
        float a3 = As[ty * 4 + 3][kk];
        float4 b4 = *(const float4*)&Bs[kk][tx * 4];
        acc[0][0] = fmaf(a0, b4.x, acc[0][0]); acc[0][1] = fmaf(a0, b4.y, acc[0][1]);
        acc[0][2] = fmaf(a0, b4.z, acc[0][2]); acc[0][3] = fmaf(a0, b4.w, acc[0][3]);
        acc[1][0] = fmaf(a1, b4.x, acc[1][0]); acc[1][1] = fmaf(a1, b4.y, acc[1][1]);
        acc[1][2] = fmaf(a1, b4.z, acc[1][2]); acc[1][3] = fmaf(a1, b4.w, acc[1][3]);
        acc[2][0] = fmaf(a2, b4.x, acc[2][0]); acc[2][1] = fmaf(a2, b4.y, acc[2][1]);
        acc[2][2] = fmaf(a2, b4.z, acc[2][2]); acc[2][3] = fmaf(a2, b4.w, acc[2][3]);
        acc[3][0] = fmaf(a3, b4.x, acc[3][0]); acc[3][1] = fmaf(a3, b4.y, acc[3][1]);
        acc[3][2] = fmaf(a3, b4.z, acc[3][2]); acc[3][3] = fmaf(a3, b4.w, acc[3][3]);
    }

    float4 bb = *(const float4*)&Wo_b[n0 + tx * 4];
    #pragma unroll
    for (int i = 0; i < 4; i++) {
        float4 r = make_float4(acc[i][0] + bb.x, acc[i][1] + bb.y,
                               acc[i][2] + bb.z, acc[i][3] + bb.w);
        *(float4*)&out[(size_t)(m0 + ty * 4 + i) * DMODEL + n0 + tx * 4] = r;
    }
}

// ------------------------- launch --------------------------------------------
extern "C" void kernel_launch(void* const* d_in, const int* in_sizes, int n_in,
                              void* d_out, int out_size) {
    const float* Q    = (const float*)d_in[0];
    const float* K    = (const float*)d_in[1];
    const float* V    = (const float*)d_in[2];
    const float* WQ_w = (const float*)d_in[3];
    const float* WQ_b = (const float*)d_in[4];
    const float* WK_w = (const float*)d_in[5];
    const float* WK_b = (const float*)d_in[6];
    const float* WV_w = (const float*)d_in[7];
    const float* WV_b = (const float*)d_in[8];
    const float* Wo_w = (const float*)d_in[9];
    const float* Wo_b = (const float*)d_in[10];
    float* out = (float*)d_out;

    dim3 gproj(B_SZ * S_LEN / 64, 1, 3);
    proj_kernel<<<gproj, 256>>>(Q, K, V, WQ_w, WQ_b, WK_w, WK_b, WV_w, WV_b);

    weff_kernel<<<(DK * DMODEL) / 256, 256>>>(Wo_w);

    dim3 gattn(MAXCH, NT, B_SZ);
    attn_partial_kernel<<<gattn, 128>>>();

    dim3 gmerge(NT, B_SZ);
    attn_merge_kernel<<<gmerge, 128>>>();

    dim3 gout(B_SZ * S_LEN / 64, DMODEL / 64);
    outproj_kernel<<<gout, 256>>>(Wo_b, out);
}

// round 7
// speedup vs baseline: 1.9333x; 1.9333x over previous
#include <cuda_runtime.h>
#include <math.h>

#define S_LEN  2048
#define B_SZ   4
#define DMODEL 512
#define DK     64
#define BM     128      // query rows per attention block (== threads)
#define KC     256      // keys per split-KV chunk
#define SUBK   64       // keys per SMEM subtile
#define NT     (S_LEN / BM)   // 16 query tiles per batch
#define MAXCH  (S_LEN / KC)   // 8 chunks max

typedef unsigned long long u64;

// ---- packed fp32x2 helpers (ptxas never emits FFMA2 from C++; PTX only) ----
__device__ __forceinline__ u64 pack2(float lo, float hi) {
    u64 r; asm("mov.b64 %0, {%1, %2};" : "=l"(r) : "f"(lo), "f"(hi)); return r;
}
__device__ __forceinline__ void ffma2(u64& d, u64 a, u64 b) {
    asm("fma.rn.f32x2 %0, %1, %2, %0;" : "+l"(d) : "l"(a), "l"(b));
}
__device__ __forceinline__ void fmul2(u64& d, u64 a) {
    asm("mul.rn.f32x2 %0, %0, %1;" : "+l"(d) : "l"(a));
}
__device__ __forceinline__ float2 unpack2(u64 v) {
    float2 f; asm("mov.b64 {%0, %1}, %2;" : "=f"(f.x), "=f"(f.y) : "l"(v)); return f;
}

// ------------------------- scratch (no mallocs allowed) -------------------------
__device__ float g_q   [B_SZ * S_LEN * DK];
__device__ float g_k   [B_SZ * S_LEN * DK];
__device__ float g_v   [B_SZ * S_LEN * DK];
__device__ float g_ho  [B_SZ * S_LEN * DK];
__device__ float g_weff[DK * DMODEL];
__device__ float g_po  [(size_t)B_SZ * NT * MAXCH * BM * DK];
__device__ float g_pml [(size_t)B_SZ * NT * MAXCH * BM * 2];

// ------------------------- 1) fused q/k/v projections -------------------------
// GEMM: out[8192,64] = X[8192,512] @ W[512,64] + b.  blockIdx.z selects q/k/v.
// Tile: 64 rows x 64 cols, 256 threads (16x16), 4x4 microtile, f32x2 FMA.
__global__ __launch_bounds__(256) void proj_kernel(
    const float* __restrict__ Q, const float* __restrict__ K, const float* __restrict__ V,
    const float* __restrict__ WQ, const float* __restrict__ bQ,
    const float* __restrict__ WK, const float* __restrict__ bK,
    const float* __restrict__ WV, const float* __restrict__ bV)
{
    const float* X; const float* W; const float* bias; float* out;
    if (blockIdx.z == 0)      { X = Q; W = WQ; bias = bQ; out = g_q; }
    else if (blockIdx.z == 1) { X = K; W = WK; bias = bK; out = g_k; }
    else                      { X = V; W = WV; bias = bV; out = g_v; }

    __shared__ float Xs[64][33];   // padded: avoid bank conflict on row reads
    __shared__ float Ws[32][64];

    const int tid = threadIdx.x;
    const int tx = tid & 15, ty = tid >> 4;
    const int m0 = blockIdx.x * 64;

    u64 acc2[4][2];
    #pragma unroll
    for (int i = 0; i < 4; i++) { acc2[i][0] = 0ull; acc2[i][1] = 0ull; }

    for (int k0 = 0; k0 < DMODEL; k0 += 32) {
        __syncthreads();
        // Xs: 64 rows x 32 cols = 512 float4
        #pragma unroll
        for (int it = 0; it < 2; it++) {
            int idx = tid + it * 256;          // 0..511
            int row = idx >> 3;                // 8 float4 per row
            int c4  = idx & 7;
            float4 v4 = *(const float4*)(X + (size_t)(m0 + row) * DMODEL + k0 + c4 * 4);
            Xs[row][c4 * 4 + 0] = v4.x; Xs[row][c4 * 4 + 1] = v4.y;
            Xs[row][c4 * 4 + 2] = v4.z; Xs[row][c4 * 4 + 3] = v4.w;
        }
        // Ws: 32 rows x 64 cols = 512 float4
        #pragma unroll
        for (int it = 0; it < 2; it++) {
            int idx = tid + it * 256;
            int row = idx >> 4;                // 16 float4 per row
            int c4  = idx & 15;
            float4 v4 = *(const float4*)(W + (size_t)(k0 + row) * DK + c4 * 4);
            *(float4*)&Ws[row][c4 * 4] = v4;
        }
        __syncthreads();

        #pragma unroll
        for (int kk = 0; kk < 32; kk++) {
            u64 pa0 = pack2(Xs[ty * 4 + 0][kk], Xs[ty * 4 + 0][kk]);
            u64 pa1 = pack2(Xs[ty * 4 + 1][kk], Xs[ty * 4 + 1][kk]);
            u64 pa2 = pack2(Xs[ty * 4 + 2][kk], Xs[ty * 4 + 2][kk]);
            u64 pa3 = pack2(Xs[ty * 4 + 3][kk], Xs[ty * 4 + 3][kk]);
            ulonglong2 b2 = *(const ulonglong2*)&Ws[kk][tx * 4];
            ffma2(acc2[0][0], pa0, b2.x); ffma2(acc2[0][1], pa0, b2.y);
            ffma2(acc2[1][0], pa1, b2.x); ffma2(acc2[1][1], pa1, b2.y);
            ffma2(acc2[2][0], pa2, b2.x); ffma2(acc2[2][1], pa2, b2.y);
            ffma2(acc2[3][0], pa3, b2.x); ffma2(acc2[3][1], pa3, b2.y);
        }
    }

    float4 bb = *(const float4*)&bias[tx * 4];
    #pragma unroll
    for (int i = 0; i < 4; i++) {
        float2 c0 = unpack2(acc2[i][0]);
        float2 c1 = unpack2(acc2[i][1]);
        float4 r = make_float4(c0.x + bb.x, c0.y + bb.y, c1.x + bb.z, c1.y + bb.w);
        *(float4*)&out[(size_t)(m0 + ty * 4 + i) * DK + tx * 4] = r;
    }
}

// ------------------------- 2) W_eff = sum over 8 head-blocks of Wo_w ----------
// tile(head_out, 8) @ Wo == head_out @ (sum of 8 row-blocks of Wo)
__global__ void weff_kernel(const float* __restrict__ Wo) {
    int idx = blockIdx.x * 256 + threadIdx.x;  // 64*512 = 32768 elements
    int r = idx >> 9;
    int c = idx & 511;
    float s = 0.f;
    #pragma unroll
    for (int h = 0; h < 8; h++) s += Wo[(size_t)((h << 6) + r) * DMODEL + c];
    g_weff[idx] = s;
}

// ------------------------- 3) split-KV flash attention partials ---------------
// One thread owns one query row: q[64], o[64] packed as f32x2 in registers.
__global__ __launch_bounds__(128) void attn_partial_kernel() {
    const int b = blockIdx.z;
    const int t = blockIdx.y;
    const int chunk = blockIdx.x;
    const int kbeg = chunk * KC;
    const int kend = min(kbeg + KC, (t + 1) * BM);
    if (kbeg >= kend) return;  // uniform across block (no sync before this)

    const int tid = threadIdx.x;
    const int qrow = t * BM + tid;

    const float* qptr = g_q + ((size_t)b * S_LEN + qrow) * DK;
    u64 q2[32];
    {
        const ulonglong2* qp2 = (const ulonglong2*)qptr;
        #pragma unroll
        for (int i = 0; i < 16; i++) { ulonglong2 v = qp2[i]; q2[2*i] = v.x; q2[2*i+1] = v.y; }
    }

    __shared__ float Ks[SUBK][DK];
    __shared__ float Vs[SUBK][DK];

    float m = -INFINITY, l = 0.f;
    u64 o2[32];
    #pragma unroll
    for (int i = 0; i < 32; i++) o2[i] = 0ull;   // bit pattern {0f,0f}

    const int lrow = tid >> 1, half = tid & 1;

    for (int ks = kbeg; ks < kend; ks += SUBK) {
        __syncthreads();
        {   // cooperative load: 64 rows x 64 floats each for K and V
            const float4* kg = (const float4*)(g_k + ((size_t)b * S_LEN + ks + lrow) * DK + half * 32);
            const float4* vg = (const float4*)(g_v + ((size_t)b * S_LEN + ks + lrow) * DK + half * 32);
            float4* kd = (float4*)&Ks[lrow][half * 32];
            float4* vd = (float4*)&Vs[lrow][half * 32];
            #pragma unroll
            for (int i = 0; i < 8; i++) kd[i] = kg[i];
            #pragma unroll
            for (int i = 0; i < 8; i++) vd[i] = vg[i];
        }
        __syncthreads();

        const int jmax = min(SUBK, qrow - ks + 1);   // causal bound for this row
        #pragma unroll 2
        for (int j = 0; j < jmax; j++) {
            const ulonglong2* kk2 = (const ulonglong2*)&Ks[j][0];
            u64 a0 = 0ull, a1 = 0ull, a2 = 0ull, a3 = 0ull;
            #pragma unroll
            for (int i = 0; i < 4; i++) {
                ulonglong2 ka = kk2[4*i + 0]; ffma2(a0, q2[8*i + 0], ka.x); ffma2(a1, q2[8*i + 1], ka.y);
                ulonglong2 kb = kk2[4*i + 1]; ffma2(a2, q2[8*i + 2], kb.x); ffma2(a3, q2[8*i + 3], kb.y);
                ulonglong2 kc = kk2[4*i + 2]; ffma2(a0, q2[8*i + 4], kc.x); ffma2(a1, q2[8*i + 5], kc.y);
                ulonglong2 kd = kk2[4*i + 3]; ffma2(a2, q2[8*i + 6], kd.x); ffma2(a3, q2[8*i + 7], kd.y);
            }
            float2 f0 = unpack2(a0), f1 = unpack2(a1), f2 = unpack2(a2), f3 = unpack2(a3);
            float s = (((f0.x + f0.y) + (f1.x + f1.y)) + ((f2.x + f2.y) + (f3.x + f3.y))) * 0.125f;

            if (s > m) {              // rare online-softmax rescale
                float cor = __expf(m - s);   // m=-inf first time -> 0, o already 0
                l *= cor;
                u64 cor2 = pack2(cor, cor);
                #pragma unroll
                for (int d = 0; d < 32; d++) fmul2(o2[d], cor2);
                m = s;
            }
            float p = __expf(s - m);
            l += p;
            u64 pp = pack2(p, p);
            const ulonglong2* vv2 = (const ulonglong2*)&Vs[j][0];
            #pragma unroll
            for (int i = 0; i < 16; i++) {
                ulonglong2 v = vv2[i];
                ffma2(o2[2*i + 0], pp, v.x);
                ffma2(o2[2*i + 1], pp, v.y);
            }
        }
    }

    const size_t base = (((size_t)b * NT + t) * MAXCH + chunk) * BM + tid;
    ulonglong2* po2 = (ulonglong2*)(g_po + base * DK);
    #pragma unroll
    for (int i = 0; i < 16; i++) {
        ulonglong2 v; v.x = o2[2*i]; v.y = o2[2*i + 1];
        po2[i] = v;
    }
    *(float2*)&g_pml[base * 2] = make_float2(m, l);
}

// ------------------------- 4) merge split-KV partials -------------------------
// 512 threads: each owns (row, 16-float segment). m/l prefetched for MLP.
__global__ __launch_bounds__(512) void attn_merge_kernel() {
    const int b = blockIdx.y, t = blockIdx.x;
    const int tid = threadIdx.x;
    const int row = tid >> 2;        // 0..127
    const int seg = tid & 3;         // 16-float segment of DK
    const int nch = ((t + 1) * BM + KC - 1) / KC;  // active chunks for this tile
    const size_t base0 = (((size_t)b * NT + t) * MAXCH) * BM + row;

    float mc[MAXCH], lc[MAXCH];
    float mstar = -INFINITY;
    for (int c = 0; c < nch; c++) {
        float2 ml = *(const float2*)&g_pml[(base0 + (size_t)c * BM) * 2];
        mc[c] = ml.x; lc[c] = ml.y;
        mstar = fmaxf(mstar, ml.x);
    }

    float lsum = 0.f;
    float o[16];
    #pragma unroll
    for (int i = 0; i < 16; i++) o[i] = 0.f;

    for (int c = 0; c < nch; c++) {
        float w = __expf(mc[c] - mstar);
        lsum += lc[c] * w;
        const float4* po = (const float4*)(g_po + (base0 + (size_t)c * BM) * DK + seg * 16);
        #pragma unroll
        for (int i = 0; i < 4; i++) {
            float4 v4 = po[i];
            o[i*4 + 0] = fmaf(w, v4.x, o[i*4 + 0]);
            o[i*4 + 1] = fmaf(w, v4.y, o[i*4 + 1]);
            o[i*4 + 2] = fmaf(w, v4.z, o[i*4 + 2]);
            o[i*4 + 3] = fmaf(w, v4.w, o[i*4 + 3]);
        }
    }
    float inv = 1.f / lsum;
    float* out = g_ho + ((size_t)b * S_LEN + t * BM + row) * DK + seg * 16;
    #pragma unroll
    for (int i = 0; i < 4; i++)
        *(float4*)(out + i * 4) = make_float4(o[i*4+0] * inv, o[i*4+1] * inv,
                                              o[i*4+2] * inv, o[i*4+3] * inv);
}

// ------------------------- 5) output GEMM: ho @ W_eff + Wo_b ------------------
// out[8192,512] = ho[8192,64] @ g_weff[64,512] + b. Tile 64x64, K=64, f32x2.
__global__ __launch_bounds__(256) void outproj_kernel(
    const float* __restrict__ Wo_b, float* __restrict__ out)
{
    __shared__ float As[64][65];
    __shared__ float Bs[64][64];

    const int tid = threadIdx.x;
    const int tx = tid & 15, ty = tid >> 4;
    const int m0 = blockIdx.x * 64;
    const int n0 = blockIdx.y * 64;

    // As: 64x64 = 1024 float4
    #pragma unroll
    for (int it = 0; it < 4; it++) {
        int idx = tid + it * 256;
        int row = idx >> 4;
        int c4  = idx & 15;
        float4 v4 = *(const float4*)(g_ho + (size_t)(m0 + row) * DK + c4 * 4);
        As[row][c4 * 4 + 0] = v4.x; As[row][c4 * 4 + 1] = v4.y;
        As[row][c4 * 4 + 2] = v4.z; As[row][c4 * 4 + 3] = v4.w;
    }
    // Bs: 64 rows (k) x 64 cols of g_weff
    #pragma unroll
    for (int it = 0; it < 4; it++) {
        int idx = tid + it * 256;
        int row = idx >> 4;
        int c4  = idx & 15;
        float4 v4 = *(const float4*)(g_weff + (size_t)row * DMODEL + n0 + c4 * 4);
        *(float4*)&Bs[row][c4 * 4] = v4;
    }
    __syncthreads();

    u64 acc2[4][2];
    #pragma unroll
    for (int i = 0; i < 4; i++) { acc2[i][0] = 0ull; acc2[i][1] = 0ull; }

    #pragma unroll
    for (int kk = 0; kk < 64; kk++) {
        u64 pa0 = pack2(As[ty * 4 + 0][kk], As[ty * 4 + 0][kk]);
        u64 pa1 = pack2(As[ty * 4 + 1][kk], As[ty * 4 + 1][kk]);
        u64 pa2 = pack2(As[ty * 4 + 2][kk], As[ty * 4 + 2][kk]);
        u64 pa3 = pack2(As[ty * 4 + 3][kk], As[ty * 4 + 3][kk]);
        ulonglong2 b2 = *(const ulonglong2*)&Bs[kk][tx * 4];
        ffma2(acc2[0][0], pa0, b2.x); ffma2(acc2[0][1], pa0, b2.y);
        ffma2(acc2[1][0], pa1, b2.x); ffma2(acc2[1][1], pa1, b2.y);
        ffma2(acc2[2][0], pa2, b2.x); ffma2(acc2[2][1], pa2, b2.y);
        ffma2(acc2[3][0], pa3, b2.x); ffma2(acc2[3][1], pa3, b2.y);
    }

    float4 bb = *(const float4*)&Wo_b[n0 + tx * 4];
    #pragma unroll
    for (int i = 0; i < 4; i++) {
        float2 c0 = unpack2(acc2[i][0]);
        float2 c1 = unpack2(acc2[i][1]);
        float4 r = make_float4(c0.x + bb.x, c0.y + bb.y, c1.x + bb.z, c1.y + bb.w);
        *(float4*)&out[(size_t)(m0 + ty * 4 + i) * DMODEL + n0 + tx * 4] = r;
    }
}

// ------------------------- launch --------------------------------------------
extern "C" void kernel_launch(void* const* d_in, const int* in_sizes, int n_in,
                              void* d_out, int out_size) {
    const float* Q    = (const float*)d_in[0];
    const float* K    = (const float*)d_in[1];
    const float* V    = (const float*)d_in[2];
    const float* WQ_w = (const float*)d_in[3];
    const float* WQ_b = (const float*)d_in[4];
    const float* WK_w = (const float*)d_in[5];
    const float* WK_b = (const float*)d_in[6];
    const float* WV_w = (const float*)d_in[7];
    const float* WV_b = (const float*)d_in[8];
    const float* Wo_w = (const float*)d_in[9];
    const float* Wo_b = (const float*)d_in[10];
    float* out = (float*)d_out;

    dim3 gproj(B_SZ * S_LEN / 64, 1, 3);
    proj_kernel<<<gproj, 256>>>(Q, K, V, WQ_w, WQ_b, WK_w, WK_b, WV_w, WV_b);

    weff_kernel<<<(DK * DMODEL) / 256, 256>>>(Wo_w);

    dim3 gattn(MAXCH, NT, B_SZ);
    attn_partial_kernel<<<gattn, 128>>>();

    dim3 gmerge(NT, B_SZ);
    attn_merge_kernel<<<gmerge, 512>>>();

    dim3 gout(B_SZ * S_LEN / 64, DMODEL / 64);
    outproj_kernel<<<gout, 256>>>(Wo_b, out);
}